// round 6
// baseline (speedup 1.0000x reference)
#include <cuda_runtime.h>
#include <cstdint>

#define BH    8
#define DK    64
#define DVV   64
#define NSEQ  2048
#define MF    128
#define CHUNK 128
#define NC    16
#define VP    72          // DV padded: col 64 = ones (z / norm), 65..71 = 0

#define PHI_SCALE 0.08838834764831845f   // 1/sqrt(128)

// Per-(head,chunk) fused state [S | z | pad] : [m][VP], fp32 (kB -> excl prefix)
__device__ float    g_S [BH * NC * MF * VP];      // 4.7 MB
// tf32-bit spills of the feature maps (computed in kA, consumed in kC)
__device__ uint32_t g_PK[BH * NC * MF * CHUNK];   // phi_k^T  [m][i]  8 MB
__device__ uint32_t g_PQ[BH * NC * MF * CHUNK];   // phi_q    [i][m]  8 MB

// ---------------------------------------------------------------------------
__device__ __forceinline__ uint32_t f2tf(float f) {
    uint32_t r; asm("cvt.rna.tf32.f32 %0, %1;" : "=r"(r) : "f"(f)); return r;
}
__device__ __forceinline__ void mma8(float* d, const uint32_t* A, const uint32_t* B) {
    asm volatile("mma.sync.aligned.m16n8k8.row.col.f32.tf32.tf32.f32 "
                 "{%0,%1,%2,%3}, {%4,%5,%6,%7}, {%8,%9}, {%0,%1,%2,%3};"
                 : "+f"(d[0]), "+f"(d[1]), "+f"(d[2]), "+f"(d[3])
                 : "r"(A[0]), "r"(A[1]), "r"(A[2]), "r"(A[3]), "r"(B[0]), "r"(B[1]));
}

// Strides (words): A-operand tiles ≡4 (mod 32), B-operand tiles ≡8 (mod 32).
#define STR_KQ 68
#define STR_F  136
#define STR_PT 132
#define STR_V  72
#define STR_PK 136
#define STR_PQ 132
#define STR_ST 72

// ===========================================================================
// Kernel A (512 thr): phi_k, phi_q = relu(X F^T)*s ; [S|z] = phi_k^T [V;1];
// spill phi_k^T -> g_PK, phi_q -> g_PQ.
// ===========================================================================
#define A_K   0        // 128x68  = 8704
#define A_Q   8704     // 128x68  = 8704
#define A_F   17408    // 64x136  = 8704
#define A_PT  26112    // 128x132 = 16896 (phi_k^T [m][i], then phi_q [i][m])
#define A_V   43008    // 128x72  = 9216
#define A_SMW 52224
#define A_SMB (A_SMW * 4)

__global__ void __launch_bounds__(512, 1)
kA(const float* __restrict__ keys, const float* __restrict__ values,
   const float* __restrict__ queries, const float* __restrict__ feat)
{
    extern __shared__ uint32_t sm[];
    const int t = threadIdx.x, w = t >> 5, lane = t & 31;
    const int g = lane >> 2, tg = lane & 3;
    const int c = blockIdx.x, h = blockIdx.y, nbase = c * CHUNK;
    const size_t hc = (size_t)(h * NC + c);

    // ---- stage (vectorized, tf32-rounded) ----
    for (int idx = t; idx < DK * 32; idx += 512) {
        int d = idx >> 5, i4 = (idx & 31) << 2;
        float4 xk = *(const float4*)&keys   [(h * DK + d) * NSEQ + nbase + i4];
        float4 xq = *(const float4*)&queries[(h * DK + d) * NSEQ + nbase + i4];
        sm[A_K + (i4 + 0) * STR_KQ + d] = f2tf(xk.x);
        sm[A_K + (i4 + 1) * STR_KQ + d] = f2tf(xk.y);
        sm[A_K + (i4 + 2) * STR_KQ + d] = f2tf(xk.z);
        sm[A_K + (i4 + 3) * STR_KQ + d] = f2tf(xk.w);
        sm[A_Q + (i4 + 0) * STR_KQ + d] = f2tf(xq.x);
        sm[A_Q + (i4 + 1) * STR_KQ + d] = f2tf(xq.y);
        sm[A_Q + (i4 + 2) * STR_KQ + d] = f2tf(xq.z);
        sm[A_Q + (i4 + 3) * STR_KQ + d] = f2tf(xq.w);
    }
    for (int idx = t; idx < DVV * 32; idx += 512) {
        int v = idx >> 5, i4 = (idx & 31) << 2;
        float4 x = *(const float4*)&values[(h * DVV + v) * NSEQ + nbase + i4];
        sm[A_V + (i4 + 0) * STR_V + v] = f2tf(x.x);
        sm[A_V + (i4 + 1) * STR_V + v] = f2tf(x.y);
        sm[A_V + (i4 + 2) * STR_V + v] = f2tf(x.z);
        sm[A_V + (i4 + 3) * STR_V + v] = f2tf(x.w);
    }
    for (int idx = t; idx < MF * 16; idx += 512) {
        int m = idx >> 4, d4 = (idx & 15) << 2;
        float4 x = *(const float4*)&feat[m * DK + d4];
        sm[A_F + (d4 + 0) * STR_F + m] = f2tf(x.x);
        sm[A_F + (d4 + 1) * STR_F + m] = f2tf(x.y);
        sm[A_F + (d4 + 2) * STR_F + m] = f2tf(x.z);
        sm[A_F + (d4 + 3) * STR_F + m] = f2tf(x.w);
    }
    for (int idx = t; idx < CHUNK * 8; idx += 512) {
        int i = idx >> 3, v = 64 + (idx & 7);
        sm[A_V + i * STR_V + v] = (v == 64) ? 0x3F800000u : 0u;
    }
    __syncthreads();

    const int wm0 = (w & 3) * 32, wn0 = (w >> 2) * 32;

    // ---- GEMM1a: phi_k [i][m], warp tile 32x32 ----
    {
        float D[2][4][4] = {};
        for (int kk = 0; kk < 64; kk += 8) {
            uint32_t A[2][4], B[4][2];
            #pragma unroll
            for (int ms = 0; ms < 2; ms++) {
                int r0 = wm0 + ms * 16 + g;
                A[ms][0] = sm[A_K + r0 * STR_KQ + kk + tg];
                A[ms][1] = sm[A_K + (r0 + 8) * STR_KQ + kk + tg];
                A[ms][2] = sm[A_K + r0 * STR_KQ + kk + tg + 4];
                A[ms][3] = sm[A_K + (r0 + 8) * STR_KQ + kk + tg + 4];
            }
            #pragma unroll
            for (int ns = 0; ns < 4; ns++) {
                B[ns][0] = sm[A_F + (kk + tg) * STR_F + wn0 + ns * 8 + g];
                B[ns][1] = sm[A_F + (kk + tg + 4) * STR_F + wn0 + ns * 8 + g];
            }
            #pragma unroll
            for (int ms = 0; ms < 2; ms++)
                #pragma unroll
                for (int ns = 0; ns < 4; ns++) mma8(D[ms][ns], A[ms], B[ns]);
        }
        // epilogue: relu*scale -> phi_k^T [m][i] (conflict-free)
        #pragma unroll
        for (int ms = 0; ms < 2; ms++)
            #pragma unroll
            for (int ns = 0; ns < 4; ns++)
                #pragma unroll
                for (int e = 0; e < 4; e++) {
                    int ri = wm0 + ms * 16 + g + ((e >> 1) << 3);
                    int cm = wn0 + ns * 8 + tg * 2 + (e & 1);
                    sm[A_PT + cm * STR_PT + ri] =
                        f2tf(fmaxf(D[ms][ns][e], 0.f) * PHI_SCALE);
                }
    }
    __syncthreads();

    // ---- GEMM2: [S|z] = phi_k^T [V;1], 16 warps: 8 M-tiles x 2 N-halves ----
    {
        const int m0 = (w >> 1) * 16, half = w & 1;
        const int nsB = half ? 5 : 0, nsC = half ? 4 : 5;
        float D[5][4] = {};
        for (int kk = 0; kk < CHUNK; kk += 8) {
            uint32_t A[4];
            A[0] = sm[A_PT + (m0 + g) * STR_PT + kk + tg];
            A[1] = sm[A_PT + (m0 + g + 8) * STR_PT + kk + tg];
            A[2] = sm[A_PT + (m0 + g) * STR_PT + kk + tg + 4];
            A[3] = sm[A_PT + (m0 + g + 8) * STR_PT + kk + tg + 4];
            #pragma unroll
            for (int s = 0; s < 5; s++) {
                if (s >= nsC) break;
                int ns = nsB + s;
                uint32_t B[2];
                B[0] = sm[A_V + (kk + tg) * STR_V + ns * 8 + g];
                B[1] = sm[A_V + (kk + tg + 4) * STR_V + ns * 8 + g];
                mma8(D[s], A, B);
            }
        }
        float* Sg = g_S + hc * MF * VP;
        #pragma unroll
        for (int s = 0; s < 5; s++) {
            if (s >= nsC) break;
            #pragma unroll
            for (int e = 0; e < 4; e++) {
                int row = m0 + g + ((e >> 1) << 3);
                int col = (nsB + s) * 8 + tg * 2 + (e & 1);
                Sg[row * VP + col] = D[s][e];
            }
        }
    }
    // spill phi_k^T -> g_PK (compact [m][i]), uint4
    {
        uint32_t* dst = g_PK + hc * MF * CHUNK;
        for (int idx = t; idx < MF * 32; idx += 512) {
            int m = idx >> 5, i4 = (idx & 31) << 2;
            *(uint4*)&dst[m * CHUNK + i4] = *(const uint4*)&sm[A_PT + m * STR_PT + i4];
        }
    }
    __syncthreads();   // GEMM2 + spill reads of phiT done

    // ---- GEMM1b: phi_q [i][m] -> reuse A_PT region as [i][m] ----
    {
        float D[2][4][4] = {};
        for (int kk = 0; kk < 64; kk += 8) {
            uint32_t A[2][4], B[4][2];
            #pragma unroll
            for (int ms = 0; ms < 2; ms++) {
                int r0 = wm0 + ms * 16 + g;
                A[ms][0] = sm[A_Q + r0 * STR_KQ + kk + tg];
                A[ms][1] = sm[A_Q + (r0 + 8) * STR_KQ + kk + tg];
                A[ms][2] = sm[A_Q + r0 * STR_KQ + kk + tg + 4];
                A[ms][3] = sm[A_Q + (r0 + 8) * STR_KQ + kk + tg + 4];
            }
            #pragma unroll
            for (int ns = 0; ns < 4; ns++) {
                B[ns][0] = sm[A_F + (kk + tg) * STR_F + wn0 + ns * 8 + g];
                B[ns][1] = sm[A_F + (kk + tg + 4) * STR_F + wn0 + ns * 8 + g];
            }
            #pragma unroll
            for (int ms = 0; ms < 2; ms++)
                #pragma unroll
                for (int ns = 0; ns < 4; ns++) mma8(D[ms][ns], A[ms], B[ns]);
        }
        #pragma unroll
        for (int ms = 0; ms < 2; ms++)
            #pragma unroll
            for (int ns = 0; ns < 4; ns++)
                #pragma unroll
                for (int e = 0; e < 4; e++) {
                    int ri = wm0 + ms * 16 + g + ((e >> 1) << 3);
                    int cm = wn0 + ns * 8 + tg * 2 + (e & 1);
                    sm[A_PT + ri * STR_PT + cm] =
                        f2tf(fmaxf(D[ms][ns][e], 0.f) * PHI_SCALE);
                }
    }
    __syncthreads();
    // spill phi_q -> g_PQ (compact [i][m]), uint4
    {
        uint32_t* dst = g_PQ + hc * MF * CHUNK;
        for (int idx = t; idx < MF * 32; idx += 512) {
            int i = idx >> 5, m4 = (idx & 31) << 2;
            *(uint4*)&dst[i * MF + m4] = *(const uint4*)&sm[A_PT + i * STR_PT + m4];
        }
    }
}

// ===========================================================================
// Kernel B: exclusive prefix over chunks of g_S (elementwise)
// ===========================================================================
__global__ void __launch_bounds__(256, 1) kB()
{
    const int h = blockIdx.x, idx = blockIdx.y * 256 + threadIdx.x;  // < 9216
    float* base = g_S + (size_t)h * NC * MF * VP + idx;
    float v[NC];
    #pragma unroll
    for (int c = 0; c < NC; c++) v[c] = base[c * (MF * VP)];
    float run = 0.f;
    #pragma unroll
    for (int c = 0; c < NC; c++) { base[c * (MF * VP)] = run; run += v[c]; }
}

// ===========================================================================
// Kernel C (512 thr): scores = mask(phiQ.phiK^T); out|norm = phiQ.St+ + Sc.V+
// ===========================================================================
#define C_PK  0        // 128x136 = 17408 (phiK^T [m][j]; later Sc [i][j] str 132)
#define C_PQ  17408    // 128x132 = 16896
#define C_ST  34304    // 128x72  = 9216
#define C_V   43520    // 128x72  = 9216
#define C_NRM 52736    // 128 floats
#define C_SMW 52864
#define C_SMB (C_SMW * 4)
#define STR_SC 132

__global__ void __launch_bounds__(512, 1)
kC(const float* __restrict__ values, float* __restrict__ out)
{
    extern __shared__ uint32_t sm[];
    const int t = threadIdx.x, w = t >> 5, lane = t & 31;
    const int g = lane >> 2, tg = lane & 3;
    const int c = blockIdx.x, h = blockIdx.y, nbase = c * CHUNK;
    const size_t hc = (size_t)(h * NC + c);

    // ---- stage ----
    {
        const uint32_t* pk = g_PK + hc * MF * CHUNK;
        const uint32_t* pq = g_PQ + hc * MF * CHUNK;
        for (int idx = t; idx < MF * 32; idx += 512) {
            int m = idx >> 5, j4 = (idx & 31) << 2;
            *(uint4*)&sm[C_PK + m * STR_PK + j4] = *(const uint4*)&pk[m * CHUNK + j4];
            *(uint4*)&sm[C_PQ + m * STR_PQ + j4] = *(const uint4*)&pq[m * CHUNK + j4];
        }
        const float* Sg = g_S + hc * MF * VP;
        for (int idx = t; idx < MF * VP; idx += 512)
            sm[C_ST + idx] = f2tf(Sg[idx]);                 // [m][v], stride 72
        for (int idx = t; idx < DVV * 32; idx += 512) {
            int v = idx >> 5, j4 = (idx & 31) << 2;
            float4 x = *(const float4*)&values[(h * DVV + v) * NSEQ + nbase + j4];
            sm[C_V + (j4 + 0) * STR_V + v] = f2tf(x.x);
            sm[C_V + (j4 + 1) * STR_V + v] = f2tf(x.y);
            sm[C_V + (j4 + 2) * STR_V + v] = f2tf(x.z);
            sm[C_V + (j4 + 3) * STR_V + v] = f2tf(x.w);
        }
        for (int idx = t; idx < CHUNK * 8; idx += 512) {
            int j = idx >> 3, v = 64 + (idx & 7);
            sm[C_V + j * STR_V + v] = (v == 64) ? 0x3F800000u : 0u;
        }
    }
    __syncthreads();

    // ---- scores GEMM: warp tile 32x32, K=128 ----
    const int wm0 = (w & 3) * 32, wn0 = (w >> 2) * 32;
    float DS[2][4][4] = {};
    for (int kk = 0; kk < CHUNK; kk += 8) {
        uint32_t A[2][4], B[4][2];
        #pragma unroll
        for (int ms = 0; ms < 2; ms++) {
            int r0 = wm0 + ms * 16 + g;
            A[ms][0] = sm[C_PQ + r0 * STR_PQ + kk + tg];
            A[ms][1] = sm[C_PQ + (r0 + 8) * STR_PQ + kk + tg];
            A[ms][2] = sm[C_PQ + r0 * STR_PQ + kk + tg + 4];
            A[ms][3] = sm[C_PQ + (r0 + 8) * STR_PQ + kk + tg + 4];
        }
        #pragma unroll
        for (int ns = 0; ns < 4; ns++) {
            B[ns][0] = sm[C_PK + (kk + tg) * STR_PK + wn0 + ns * 8 + g];
            B[ns][1] = sm[C_PK + (kk + tg + 4) * STR_PK + wn0 + ns * 8 + g];
        }
        #pragma unroll
        for (int ms = 0; ms < 2; ms++)
            #pragma unroll
            for (int ns = 0; ns < 4; ns++) mma8(DS[ms][ns], A[ms], B[ns]);
    }
    __syncthreads();   // all reads of phiK done

    // ---- mask epilogue -> Sc [i][j] (overwrites C_PK) ----
    #pragma unroll
    for (int ms = 0; ms < 2; ms++)
        #pragma unroll
        for (int ns = 0; ns < 4; ns++)
            #pragma unroll
            for (int e = 0; e < 4; e++) {
                int ri = wm0 + ms * 16 + g + ((e >> 1) << 3);
                int cj = wn0 + ns * 8 + tg * 2 + (e & 1);
                float s = (cj <= ri) ? DS[ms][ns][e] : 0.f;
                sm[C_PK + ri * STR_SC + cj] = f2tf(s);
            }
    __syncthreads();

    // ---- out GEMM: [out|norm] = phiQ.St+ + Sc.V+ ; 8 M-tiles x 2 N-halves ----
    {
        const int i0 = (w >> 1) * 16, half = w & 1;
        const int nsB = half ? 5 : 0, nsC = half ? 4 : 5;
        float D[5][4] = {};
        for (int kk = 0; kk < CHUNK; kk += 8) {          // pass 1: phiQ . St+
            uint32_t A[4];
            A[0] = sm[C_PQ + (i0 + g) * STR_PQ + kk + tg];
            A[1] = sm[C_PQ + (i0 + g + 8) * STR_PQ + kk + tg];
            A[2] = sm[C_PQ + (i0 + g) * STR_PQ + kk + tg + 4];
            A[3] = sm[C_PQ + (i0 + g + 8) * STR_PQ + kk + tg + 4];
            #pragma unroll
            for (int s = 0; s < 5; s++) {
                if (s >= nsC) break;
                int ns = nsB + s;
                uint32_t B[2];
                B[0] = sm[C_ST + (kk + tg) * STR_ST + ns * 8 + g];
                B[1] = sm[C_ST + (kk + tg + 4) * STR_ST + ns * 8 + g];
                mma8(D[s], A, B);
            }
        }
        for (int kk = 0; kk < CHUNK; kk += 8) {          // pass 2: Sc . V+
            uint32_t A[4];
            A[0] = sm[C_PK + (i0 + g) * STR_SC + kk + tg];
            A[1] = sm[C_PK + (i0 + g + 8) * STR_SC + kk + tg];
            A[2] = sm[C_PK + (i0 + g) * STR_SC + kk + tg + 4];
            A[3] = sm[C_PK + (i0 + g + 8) * STR_SC + kk + tg + 4];
            #pragma unroll
            for (int s = 0; s < 5; s++) {
                if (s >= nsC) break;
                int ns = nsB + s;
                uint32_t B[2];
                B[0] = sm[C_V + (kk + tg) * STR_V + ns * 8 + g];
                B[1] = sm[C_V + (kk + tg + 4) * STR_V + ns * 8 + g];
                mma8(D[s], A, B);
            }
        }
        // norm = col 64 (half1, local s=3, tg==0, e in {0,2}) -> sNorm
        float* sNorm = (float*)(sm + C_NRM);
        if (half && tg == 0) {
            sNorm[i0 + g]     = 1.0f / D[3][0];
            sNorm[i0 + g + 8] = 1.0f / D[3][2];
        }
        __syncthreads();
        const float iLo = sNorm[i0 + g], iHi = sNorm[i0 + g + 8];
        #pragma unroll
        for (int s = 0; s < 5; s++) {
            if (s >= nsC) break;
            int ns = nsB + s;
            if (ns == 8) continue;                       // cols 64..71: norm/pad
            #pragma unroll
            for (int e = 0; e < 4; e++) {
                int ri = i0 + g + ((e >> 1) << 3);
                int v  = ns * 8 + tg * 2 + (e & 1);
                out[(h * DVV + v) * NSEQ + nbase + ri] =
                    D[s][e] * ((e >> 1) ? iHi : iLo);
            }
        }
    }
}

// ===========================================================================
extern "C" void kernel_launch(void* const* d_in, const int* in_sizes, int n_in,
                              void* d_out, int out_size)
{
    const float* keys    = (const float*)d_in[0];
    const float* values  = (const float*)d_in[1];
    const float* queries = (const float*)d_in[2];
    const float* feat    = (const float*)d_in[3];
    float* out = (float*)d_out;

    cudaFuncSetAttribute(kA, cudaFuncAttributeMaxDynamicSharedMemorySize, A_SMB);
    cudaFuncSetAttribute(kC, cudaFuncAttributeMaxDynamicSharedMemorySize, C_SMB);

    kA<<<dim3(NC, BH), 512, A_SMB>>>(keys, values, queries, feat);
    kB<<<dim3(BH, 36), 256>>>();
    kC<<<dim3(NC, BH), 512, C_SMB>>>(values, out);
}